// round 7
// baseline (speedup 1.0000x reference)
#include <cuda_runtime.h>
#include <cstdint>

#define HD  256
#define NB  128
#define PPN 1024
#define LGN 128

// ---------------- device scratch (no allocation allowed) ----------------
__device__ __align__(16) unsigned g_EW_elem[128 * 128];
__device__ __align__(16) unsigned g_EW_abb[64 * 128];    // (E_aa + E_bb)@Wd1 + bd1
__device__ __align__(16) unsigned g_EW_lig[16 * 128];    // E_lig@Wd1 + bd1
// rows 0-255 = Wd2@Wa1_p, 256-511 = Wd2@Wa1_l, 512-513 = Wa1 contact, 514 = c0
__device__ __align__(16) float g_M[515 * HD];
__device__ __align__(16) float g_pooled[256 * HD];
__device__ __align__(8)  float g_contact[NB * 2];

// ---------------- packed helpers ----------------
__device__ __forceinline__ uint64_t pk2(float a, float b) {
    uint64_t r; asm("mov.b64 %0,{%1,%2};" : "=l"(r) : "f"(a), "f"(b)); return r;
}
__device__ __forceinline__ uint64_t pkf2(float2 v) { return pk2(v.x, v.y); }
__device__ __forceinline__ float2 upk(uint64_t v) {
    float2 r; asm("mov.b64 {%0,%1},%2;" : "=f"(r.x), "=f"(r.y) : "l"(v)); return r;
}
__device__ __forceinline__ uint64_t f2fma(uint64_t a, uint64_t b, uint64_t c) {
    uint64_t d; asm("fma.rn.f32x2 %0,%1,%2,%3;" : "=l"(d) : "l"(a), "l"(b), "l"(c)); return d;
}
__device__ __forceinline__ uint64_t f2add(uint64_t a, uint64_t b) {
    uint64_t d; asm("add.rn.f32x2 %0,%1,%2;" : "=l"(d) : "l"(a), "l"(b)); return d;
}
__device__ __forceinline__ uint64_t f2mul(uint64_t a, uint64_t b) {
    uint64_t d; asm("mul.rn.f32x2 %0,%1,%2;" : "=l"(d) : "l"(a), "l"(b)); return d;
}
__device__ __forceinline__ unsigned cvt_bf16x2(float hi, float lo) {
    unsigned u; asm("cvt.rn.bf16x2.f32 %0,%1,%2;" : "=r"(u) : "f"(hi), "f"(lo)); return u;
}
__device__ __forceinline__ unsigned bf2add(unsigned a, unsigned b) {
    unsigned r; asm("add.rn.bf16x2 %0,%1,%2;" : "=r"(r) : "r"(a), "r"(b)); return r;
}
__device__ __forceinline__ uint64_t bf2_to_f2(unsigned u) {
    return pk2(__uint_as_float(u << 16), __uint_as_float(u & 0xffff0000u));
}

// =====================================================================
// K_pre v3: grid 147 x 512, dynamic smem 53248 B. 5 rows/block.
//   blk 0..41  : EW rows  r0 = blk*5        (valid gr < 208), W = Wd1
//   blk 42..93 : M_p rows lr0 = (blk-42)*5  (valid lr < 256), W = Wa1
//   blk 94..145: M_l rows lr0 = (blk-94)*5  (valid lr < 256), W = Wa1+256*HD
//   blk 146    : c0 + contact-weight rows
// Thread (ks = tid>>6 of 8 k-slices x 32, jt = tid&63 -> 4 j = 2 j-pairs).
// sE stored pre-duplicated u64 per (k,row), stride 6 u64 (48B, 16B-aligned).
// =====================================================================
__global__ __launch_bounds__(512) void k_pre(
    const float* __restrict__ E_elem, const float* __restrict__ E_aa,
    const float* __restrict__ E_bb,   const float* __restrict__ E_lig,
    const float* __restrict__ Wd1,    const float* __restrict__ bd1,
    const float* __restrict__ Wd2,    const float* __restrict__ bd2,
    const float* __restrict__ Wa1,    const float* __restrict__ ba1)
{
    extern __shared__ __align__(16) uint64_t smu[];
    uint64_t* sEd    = smu;              // 256*6 u64 = 12KB
    uint64_t* s_part = smu + 256 * 6;    // 512*10 u64 = 40KB
    const int blk = blockIdx.x;
    const int tid = threadIdx.x;

    if (blk == 146) {
        // ------- c0 row + contact weight rows (256 threads active) -------
        float* sb = (float*)smu;
        if (tid < 256) sb[tid] = bd2[tid];
        __syncthreads();
        if (tid < 256) {
            const int j = tid;
            float acc = 0.0f;
            #pragma unroll 8
            for (int m = 0; m < 256; m++)
                acc = fmaf(sb[m], Wa1[m * HD + j] + Wa1[(256 + m) * HD + j], acc);
            g_M[514 * HD + j] = acc + ba1[j];
            g_M[512 * HD + j] = Wa1[512 * HD + j];
            g_M[513 * HD + j] = Wa1[513 * HD + j];
        }
        return;
    }

    // ---- block classification ----
    const int seg = (blk < 42) ? 0 : (blk < 94 ? 1 : 2);
    const int lr0 = (seg == 0) ? blk * 5 : (seg == 1 ? (blk - 42) * 5 : (blk - 94) * 5);
    const int lim = (seg == 0) ? 208 : 256;
    const float* W = (seg == 0) ? Wd1 : (seg == 1 ? Wa1 : Wa1 + 256 * HD);

    // ---- stage sEd[k*6 + r] = dup(source value), r = 0..4; slot 5 = pad ----
    {
        const int k = tid & 255;
        const int rs = tid >> 8;           // 0: rows 0-2, 1: rows 3-4 (+pad)
        const int rbeg = rs ? 3 : 0, rend = rs ? 5 : 3;
        for (int r = rbeg; r < rend; r++) {
            const int lr = lr0 + r;
            float v = 0.0f;
            if (lr < lim) {
                if (seg == 0) {
                    if (lr < 128) v = E_elem[lr * HD + k];
                    else if (lr < 192) {
                        int idx = lr - 128;
                        v = E_aa[(idx >> 1) * HD + k] + E_bb[(idx & 1) * HD + k];
                    } else v = E_lig[(lr - 192) * HD + k];
                } else {
                    v = Wd2[lr * HD + k];
                }
            }
            sEd[k * 6 + r] = pk2(v, v);
        }
        if (rs) sEd[k * 6 + 5] = 0ull;
    }
    __syncthreads();

    // ---- mainloop: k-slice of 32, 4 j columns (2 packed j-pairs) ----
    const int jt = tid & 63, ks = tid >> 6;
    const ulonglong2* W2 = (const ulonglong2*)W;   // [k*64 + jt] = 4 floats = 2 f32x2 j-pairs
    uint64_t acc[5][2];
    #pragma unroll
    for (int r = 0; r < 5; r++) { acc[r][0] = 0ull; acc[r][1] = 0ull; }

    const int kb = ks * 32;
    #pragma unroll 8
    for (int kk = 0; kk < 32; kk++) {
        const int k = kb + kk;
        ulonglong2 ww = W2[k * 64 + jt];
        const uint64_t* e = sEd + k * 6;
        ulonglong2 e01 = *(const ulonglong2*)(e);
        ulonglong2 e23 = *(const ulonglong2*)(e + 2);
        uint64_t   e4  = e[4];
        acc[0][0] = f2fma(ww.x, e01.x, acc[0][0]); acc[0][1] = f2fma(ww.y, e01.x, acc[0][1]);
        acc[1][0] = f2fma(ww.x, e01.y, acc[1][0]); acc[1][1] = f2fma(ww.y, e01.y, acc[1][1]);
        acc[2][0] = f2fma(ww.x, e23.x, acc[2][0]); acc[2][1] = f2fma(ww.y, e23.x, acc[2][1]);
        acc[3][0] = f2fma(ww.x, e23.y, acc[3][0]); acc[3][1] = f2fma(ww.y, e23.y, acc[3][1]);
        acc[4][0] = f2fma(ww.x, e4,    acc[4][0]); acc[4][1] = f2fma(ww.y, e4,    acc[4][1]);
    }

    // ---- write partials: s_part[(ks*64+jt)*10 + r*2+p] ----
    {
        uint64_t* dst = s_part + (ks * 64 + jt) * 10;
        #pragma unroll
        for (int r = 0; r < 5; r++) {
            dst[r * 2 + 0] = acc[r][0];
            dst[r * 2 + 1] = acc[r][1];
        }
    }
    __syncthreads();

    // ---- reduce 8 slices: 640 units (jt2, item), item = r*2+p ----
    for (int u = tid; u < 640; u += 512) {
        const int jt2 = u & 63, item = u >> 6;
        const int r = item >> 1, p = item & 1;
        const int lr = lr0 + r;
        if (lr >= lim) continue;
        uint64_t s = 0ull;
        #pragma unroll
        for (int sl = 0; sl < 8; sl++)
            s = f2add(s, s_part[(sl * 64 + jt2) * 10 + item]);
        const int j0 = jt2 * 4 + p * 2;
        float2 v = upk(s);
        if (seg == 0) {
            if (lr >= 128) {
                float2 bb = *(const float2*)(bd1 + j0);
                v.x += bb.x; v.y += bb.y;
            }
            unsigned w = cvt_bf16x2(v.y, v.x);
            const int col = jt2 * 2 + p;
            if (lr < 128)      g_EW_elem[lr * 128 + col] = w;
            else if (lr < 192) g_EW_abb[(lr - 128) * 128 + col] = w;
            else               g_EW_lig[(lr - 192) * 128 + col] = w;
        } else {
            const int mr = (seg == 2 ? 256 : 0) + lr;
            *(float2*)(g_M + mr * HD + j0) = v;
        }
    }
}

// =====================================================================
// K_bc: grid 384 x 256, dynamic smem 110592B.  (unchanged)
// =====================================================================
__global__ __launch_bounds__(256, 1) void k_bc(
    const float* __restrict__ ppos, const float* __restrict__ lpos,
    const int* __restrict__ p_elem, const int* __restrict__ p_aa,
    const int* __restrict__ p_bb,   const int* __restrict__ l_type)
{
    extern __shared__ float smf[];
    const int blk = blockIdx.x;
    const int tid = threadIdx.x;

    if (blk < 128) {
        const int b = blk;
        unsigned* s_tab = (unsigned*)smf;
        int2*     s_off = (int2*)(s_tab + 16384 + 8192);
        float4*   s_red = (float4*)(s_off + 1024);

        {
            uint4* dst = (uint4*)s_tab;
            const uint4* src = (const uint4*)g_EW_elem;
            for (int i = tid; i < 4096; i += 256) dst[i] = src[i];
            dst = (uint4*)(s_tab + 16384);
            src = (const uint4*)g_EW_abb;
            for (int i = tid; i < 2048; i += 256) dst[i] = src[i];
        }
        const int base = b * PPN;
        for (int n = tid; n < PPN; n += 256) {
            int e = p_elem[base + n], a = p_aa[base + n], bb = p_bb[base + n];
            s_off[n] = make_int2(e * 128, 16384 + (a * 2 + bb) * 128);
        }
        __syncthreads();

        const int half = tid >> 7, tc = tid & 127;
        uint64_t accL = 0ull, accQ = 0ull;
        const int n0 = half * 512;
        #pragma unroll 8
        for (int n = n0; n < n0 + 512; n++) {
            int2 off = s_off[n];
            unsigned ue = s_tab[off.x + tc];
            unsigned ua = s_tab[off.y + tc];
            uint64_t x = bf2_to_f2(bf2add(ue, ua));
            accL = f2add(accL, x);
            accQ = f2fma(x, x, accQ);
        }
        float2 l = upk(accL), q = upk(accQ);
        s_red[tid] = make_float4(l.x, l.y, q.x, q.y);
        __syncthreads();
        if (tid < 128) {
            float4 a0 = s_red[tid], a1 = s_red[128 + tid];
            float2 r;
            r.x = (a0.x + a1.x) * (0.5f / 1024.0f) + (a0.z + a1.z) * (0.25f / 1024.0f);
            r.y = (a0.y + a1.y) * (0.5f / 1024.0f) + (a0.w + a1.w) * (0.25f / 1024.0f);
            ((float2*)g_pooled)[b * 128 + tid] = r;
        }
    } else if (blk < 256) {
        const int b = blk - 128;
        unsigned* s_tab = (unsigned*)smf;
        int*      s_t   = (int*)(s_tab + 2048);
        float4*   s_red = (float4*)(s_t + 128);

        {
            uint4* dst = (uint4*)s_tab;
            const uint4* src = (const uint4*)g_EW_lig;
            for (int i = tid; i < 512; i += 256) dst[i] = src[i];
        }
        const int base = b * LGN;
        if (tid < 128) s_t[tid] = l_type[base + tid] * 128;
        __syncthreads();

        const int half = tid >> 7, tc = tid & 127;
        uint64_t accL = 0ull, accQ = 0ull;
        const int n0 = half * 64;
        #pragma unroll 8
        for (int n = n0; n < n0 + 64; n++) {
            uint64_t x = bf2_to_f2(s_tab[s_t[n] + tc]);
            accL = f2add(accL, x);
            accQ = f2fma(x, x, accQ);
        }
        float2 l = upk(accL), q = upk(accQ);
        s_red[tid] = make_float4(l.x, l.y, q.x, q.y);
        __syncthreads();
        if (tid < 128) {
            float4 a0 = s_red[tid], a1 = s_red[128 + tid];
            float2 r;
            r.x = (a0.x + a1.x) * (0.5f / 128.0f) + (a0.z + a1.z) * (0.25f / 128.0f);
            r.y = (a0.y + a1.y) * (0.5f / 128.0f) + (a0.w + a1.w) * (0.25f / 128.0f);
            ((float2*)g_pooled)[(128 + b) * 128 + tid] = r;
        }
    } else {
        const int b = blk - 256;
        float2* sx = (float2*)smf;
        float2* sy = sx + 512;
        float2* sz = sy + 512;
        float* s_min = (float*)(sz + 512);
        float* s_sum4 = s_min + 1024;
        float* s_min4 = s_sum4 + 4;

        const float* pp = ppos + b * PPN * 3;
        for (int i = tid; i < PPN; i += 256) {
            ((float*)sx)[i] = pp[3 * i + 0];
            ((float*)sy)[i] = pp[3 * i + 1];
            ((float*)sz)[i] = pp[3 * i + 2];
        }
        __syncthreads();

        const int c = tid >> 5, lq = tid & 31;
        const float* lp = lpos + (b * LGN + lq * 4) * 3;
        uint64_t nlx[4], nly[4], nlz[4];
        #pragma unroll
        for (int q = 0; q < 4; q++) {
            float ax = -lp[3 * q + 0], ay = -lp[3 * q + 1], az = -lp[3 * q + 2];
            nlx[q] = pk2(ax, ax); nly[q] = pk2(ay, ay); nlz[q] = pk2(az, az);
        }
        float mlo[4] = {3.4e38f, 3.4e38f, 3.4e38f, 3.4e38f};
        float mhi[4] = {3.4e38f, 3.4e38f, 3.4e38f, 3.4e38f};
        const int p0 = c * 64;
        #pragma unroll 4
        for (int p = p0; p < p0 + 64; p++) {
            uint64_t px = pkf2(sx[p]), py = pkf2(sy[p]), pz = pkf2(sz[p]);
            #pragma unroll
            for (int q = 0; q < 4; q++) {
                uint64_t dx = f2add(px, nlx[q]);
                uint64_t dy = f2add(py, nly[q]);
                uint64_t dz = f2add(pz, nlz[q]);
                uint64_t d2 = f2mul(dx, dx);
                d2 = f2fma(dy, dy, d2);
                d2 = f2fma(dz, dz, d2);
                float2 v = upk(d2);
                mlo[q] = fminf(mlo[q], v.x);
                mhi[q] = fminf(mhi[q], v.y);
            }
        }
        #pragma unroll
        for (int q = 0; q < 4; q++) s_min[c * 128 + lq * 4 + q] = fminf(mlo[q], mhi[q]);
        __syncthreads();

        if (tid < 128) {
            float d2m = s_min[tid];
            #pragma unroll
            for (int cc = 1; cc < 8; cc++) d2m = fminf(d2m, s_min[cc * 128 + tid]);
            float d = sqrtf(d2m);
            float sumv = d, minv = d;
            #pragma unroll
            for (int off = 16; off > 0; off >>= 1) {
                sumv += __shfl_xor_sync(0xffffffffu, sumv, off);
                minv = fminf(minv, __shfl_xor_sync(0xffffffffu, minv, off));
            }
            if ((tid & 31) == 0) { s_sum4[tid >> 5] = sumv; s_min4[tid >> 5] = minv; }
        }
        __syncthreads();
        if (tid == 0) {
            float s = s_sum4[0] + s_sum4[1] + s_sum4[2] + s_sum4[3];
            float mn = fminf(fminf(s_min4[0], s_min4[1]), fminf(s_min4[2], s_min4[3]));
            g_contact[b * 2 + 0] = s * (1.0f / 128.0f);
            g_contact[b * 2 + 1] = mn;
        }
    }
}

// =====================================================================
// K_final: grid 64 x 512. 2 batches/block, split-K halves. (unchanged)
// =====================================================================
__global__ __launch_bounds__(512) void k_final(
    const float* __restrict__ Wa2, const float* __restrict__ ba2,
    float* __restrict__ out)
{
    __shared__ float2 s_pk[516];
    __shared__ float2 s_part[256];
    __shared__ float2 s_warp[8];
    const int tid = threadIdx.x;
    const int b0 = blockIdx.x * 2;

    for (int k = tid; k < 514; k += 512) {
        float v0, v1;
        if (k < 256)      { v0 = g_pooled[b0 * HD + k];              v1 = g_pooled[(b0 + 1) * HD + k]; }
        else if (k < 512) { v0 = g_pooled[(128 + b0) * HD + k - 256]; v1 = g_pooled[(129 + b0) * HD + k - 256]; }
        else              { v0 = g_contact[b0 * 2 + (k - 512)];       v1 = g_contact[(b0 + 1) * 2 + (k - 512)]; }
        s_pk[k] = make_float2(v0, v1);
    }
    if (tid == 0) s_pk[514] = make_float2(1.0f, 1.0f);
    __syncthreads();

    const int j = tid & 255, kh = tid >> 8;
    uint64_t acc = 0ull;
    if (kh == 0) {
        #pragma unroll 16
        for (int k = 0; k < 258; k++) {
            float w = g_M[k * HD + j];
            acc = f2fma(pkf2(s_pk[k]), pk2(w, w), acc);
        }
        s_part[j] = upk(acc);
    } else {
        #pragma unroll 16
        for (int k = 258; k < 515; k++) {
            float w = g_M[k * HD + j];
            acc = f2fma(pkf2(s_pk[k]), pk2(w, w), acc);
        }
    }
    __syncthreads();

    if (kh == 1) {
        float2 p = s_part[j], m = upk(acc);
        float x0 = p.x + m.x, x1 = p.y + m.y;
        float w2 = Wa2[j];
        float y0 = x0 * w2 / (1.0f + __expf(-x0));
        float y1 = x1 * w2 / (1.0f + __expf(-x1));
        #pragma unroll
        for (int off = 16; off > 0; off >>= 1) {
            y0 += __shfl_xor_sync(0xffffffffu, y0, off);
            y1 += __shfl_xor_sync(0xffffffffu, y1, off);
        }
        if ((tid & 31) == 0) s_warp[(tid >> 5) - 8] = make_float2(y0, y1);
    }
    __syncthreads();
    if (tid == 0) {
        float s0 = 0.0f, s1 = 0.0f;
        #pragma unroll
        for (int w = 0; w < 8; w++) { s0 += s_warp[w].x; s1 += s_warp[w].y; }
        out[b0 + 0] = s0 + ba2[0];
        out[b0 + 1] = s1 + ba2[0];
    }
}

extern "C" void kernel_launch(void* const* d_in, const int* in_sizes, int n_in,
                              void* d_out, int out_size) {
    const float* protein_pos = (const float*)d_in[0];
    const float* ligand_pos  = (const float*)d_in[1];
    const int*   p_elem      = (const int*)d_in[2];
    const int*   p_aa        = (const int*)d_in[3];
    const int*   p_bb        = (const int*)d_in[4];
    const int*   l_type      = (const int*)d_in[5];
    const float* E_elem = (const float*)d_in[8];
    const float* E_aa   = (const float*)d_in[9];
    const float* E_bb   = (const float*)d_in[10];
    const float* E_lig  = (const float*)d_in[11];
    const float* Wd1    = (const float*)d_in[12];
    const float* bd1    = (const float*)d_in[13];
    const float* Wd2    = (const float*)d_in[14];
    const float* bd2    = (const float*)d_in[15];
    const float* Wa1    = (const float*)d_in[16];
    const float* ba1    = (const float*)d_in[17];
    const float* Wa2    = (const float*)d_in[18];
    const float* ba2    = (const float*)d_in[19];
    float* out = (float*)d_out;

    const int pre_smem = (256 * 6 + 512 * 10) * 8;   // 53248 B
    cudaFuncSetAttribute(k_pre, cudaFuncAttributeMaxDynamicSharedMemorySize, pre_smem);
    const int bc_smem = 16384 * 4 + 8192 * 4 + 1024 * 8 + 256 * 16;
    cudaFuncSetAttribute(k_bc, cudaFuncAttributeMaxDynamicSharedMemorySize, bc_smem);

    k_pre<<<147, 512, pre_smem>>>(E_elem, E_aa, E_bb, E_lig, Wd1, bd1, Wd2, bd2, Wa1, ba1);
    k_bc<<<384, 256, bc_smem>>>(protein_pos, ligand_pos, p_elem, p_aa, p_bb, l_type);
    k_final<<<64, 512>>>(Wa2, ba2, out);
}